// round 17
// baseline (speedup 1.0000x reference)
#include <cuda_runtime.h>

#define W 8192

// +512 pad: tail blocks read up to ~127 floats past the last row
static __device__ __align__(16) float g_bufA[8 * 32 * W + 512];
static __device__ __align__(16) float g_bufB[8 * 32 * W + 512];

// ---- packed f32x2 helpers (sm_103a FFMA2 path) ----------------------------
__device__ __forceinline__ unsigned long long ffma2(
    unsigned long long a, unsigned long long b, unsigned long long c)
{
    unsigned long long d;
    asm("fma.rn.f32x2 %0, %1, %2, %3;" : "=l"(d) : "l"(a), "l"(b), "l"(c));
    return d;
}
__device__ __forceinline__ unsigned long long pack2(float lo, float hi)
{
    unsigned long long r;
    asm("mov.b64 %0, {%1, %2};" : "=l"(r) : "f"(lo), "f"(hi));
    return r;
}
__device__ __forceinline__ float2 unpack2(unsigned long long v)
{
    float2 r;
    asm("mov.b64 {%0, %1}, %2;" : "=f"(r.x), "=f"(r.y) : "l"(v));
    return r;
}
__device__ __forceinline__ float tanh_approx(float x)
{
    float y;
    asm("tanh.approx.f32 %0, %1;" : "=f"(y) : "f"(x));
    return y;
}

// ---------------------------------------------------------------------------
// Start conv: bufA[b,c,ti] = sum_k start_w[c,k] * x_input[b,k,8192+ti]
// ---------------------------------------------------------------------------
__global__ __launch_bounds__(128) void start_kernel(
    const float* __restrict__ x_input, const float* __restrict__ start_w)
{
    __shared__ __align__(16) float wsm[32 * 256];  // [c][k]
    const int b = blockIdx.y;
    for (int i = threadIdx.x; i < 32 * 256; i += 128) wsm[i] = start_w[i];
    __syncthreads();

    const int ti = (blockIdx.x * 128 + threadIdx.x) * 2;
    const float* xb = x_input + (size_t)b * 256 * 16384 + 8192 + ti;

    float2 acc[32];
#pragma unroll
    for (int c = 0; c < 32; c++) acc[c] = make_float2(0.f, 0.f);

    const float4* wv = (const float4*)wsm;
#pragma unroll 4
    for (int k4 = 0; k4 < 64; k4++) {
        float2 x0 = *(const float2*)(xb + (size_t)(k4 * 4 + 0) * 16384);
        float2 x1 = *(const float2*)(xb + (size_t)(k4 * 4 + 1) * 16384);
        float2 x2 = *(const float2*)(xb + (size_t)(k4 * 4 + 2) * 16384);
        float2 x3 = *(const float2*)(xb + (size_t)(k4 * 4 + 3) * 16384);
#pragma unroll
        for (int c = 0; c < 32; c++) {
            float4 w = wv[c * 64 + k4];
            acc[c].x = fmaf(w.x, x0.x, acc[c].x);
            acc[c].y = fmaf(w.x, x0.y, acc[c].y);
            acc[c].x = fmaf(w.y, x1.x, acc[c].x);
            acc[c].y = fmaf(w.y, x1.y, acc[c].y);
            acc[c].x = fmaf(w.z, x2.x, acc[c].x);
            acc[c].y = fmaf(w.z, x2.y, acc[c].y);
            acc[c].x = fmaf(w.w, x3.x, acc[c].x);
            acc[c].y = fmaf(w.w, x3.y, acc[c].y);
        }
    }
#pragma unroll
    for (int c = 0; c < 32; c++)
        *(float2*)(&g_bufA[((size_t)b * 32 + c) * W + ti]) = acc[c];
}

// ---------------------------------------------------------------------------
// GEMM-tiled WaveNet layer. Block = 128 threads, TILE = 128 positions,
// all 64 gated outputs (32 f + 32 g). Thread tile: 8 outs (4 f/g channel
// pairs) x 8 positions -> 32 ull accumulators, NO cross-thread reduction.
// smem (dynamic 49KB): sX [64 k][128 pos] 32KB | sWT [64 k][68] 17KB.
// After gated phase: z overwrites sX rows 0..31; dup'd resid weights
// overwrite sWT region. Residual = second GEMM 32x32x128.
// ---------------------------------------------------------------------------
__global__ __launch_bounds__(128, 4) void layer_kernel(
    const float* __restrict__ filt, const float* __restrict__ gate,
    const float* __restrict__ resid, int d, int tstart, int dir, int last)
{
    extern __shared__ __align__(16) float smem[];
    float* sX  = smem;          // [k*128 + pos]
    float* sWT = smem + 8192;   // [k*68 + c], c<32 filt, c>=32 gate

    const float* xin  = dir ? g_bufB : g_bufA;
    float*       xout = dir ? g_bufA : g_bufB;

    const int tid = threadIdx.x;
    const int og  = tid & 7;    // out-group: channels [og*4, og*4+4)
    const int pg  = tid >> 3;   // pos-group:  positions [pg*8, pg*8+8)
    const int b   = blockIdx.y;
    const int t0  = tstart + blockIdx.x * 128;

    const float* xb = xin + (size_t)b * 32 * W;

    // ---- stage X: row k = 2*in + tap; tap0 -> x[t-d], tap1 -> x[t] ----
#pragma unroll 8
    for (int r = 0; r < 64; r++) {
        const float* src = xb + (r >> 1) * W + ((r & 1) ? t0 : t0 - d);
        sX[r * 128 + tid] = src[tid];
    }
    // ---- stage transposed weights (row stride 68 kills bank conflicts) ----
#pragma unroll
    for (int i = tid; i < 2048; i += 128) {
        int c = i >> 6, k = i & 63;
        sWT[k * 68 + c]      = filt[i];
        sWT[k * 68 + 32 + c] = gate[i];
    }
    __syncthreads();

    // ---- gated GEMM: 64 k-steps, 32 FFMA2 per step ----
    unsigned long long aF[4][4], aG[4][4];
#pragma unroll
    for (int c = 0; c < 4; c++)
#pragma unroll
        for (int p = 0; p < 4; p++) { aF[c][p] = 0ull; aG[c][p] = 0ull; }

#pragma unroll 8
    for (int k = 0; k < 64; k++) {
        const float* xr = sX + k * 128 + pg * 8;
        ulonglong2 x01 = *(const ulonglong2*)xr;
        ulonglong2 x23 = *(const ulonglong2*)(xr + 4);
        const float* wr = sWT + k * 68 + og * 4;
        float4 wf = *(const float4*)wr;
        float4 wg = *(const float4*)(wr + 32);
        unsigned long long wd;
        wd = pack2(wf.x, wf.x);
        aF[0][0] = ffma2(wd, x01.x, aF[0][0]);
        aF[0][1] = ffma2(wd, x01.y, aF[0][1]);
        aF[0][2] = ffma2(wd, x23.x, aF[0][2]);
        aF[0][3] = ffma2(wd, x23.y, aF[0][3]);
        wd = pack2(wf.y, wf.y);
        aF[1][0] = ffma2(wd, x01.x, aF[1][0]);
        aF[1][1] = ffma2(wd, x01.y, aF[1][1]);
        aF[1][2] = ffma2(wd, x23.x, aF[1][2]);
        aF[1][3] = ffma2(wd, x23.y, aF[1][3]);
        wd = pack2(wf.z, wf.z);
        aF[2][0] = ffma2(wd, x01.x, aF[2][0]);
        aF[2][1] = ffma2(wd, x01.y, aF[2][1]);
        aF[2][2] = ffma2(wd, x23.x, aF[2][2]);
        aF[2][3] = ffma2(wd, x23.y, aF[2][3]);
        wd = pack2(wf.w, wf.w);
        aF[3][0] = ffma2(wd, x01.x, aF[3][0]);
        aF[3][1] = ffma2(wd, x01.y, aF[3][1]);
        aF[3][2] = ffma2(wd, x23.x, aF[3][2]);
        aF[3][3] = ffma2(wd, x23.y, aF[3][3]);
        wd = pack2(wg.x, wg.x);
        aG[0][0] = ffma2(wd, x01.x, aG[0][0]);
        aG[0][1] = ffma2(wd, x01.y, aG[0][1]);
        aG[0][2] = ffma2(wd, x23.x, aG[0][2]);
        aG[0][3] = ffma2(wd, x23.y, aG[0][3]);
        wd = pack2(wg.y, wg.y);
        aG[1][0] = ffma2(wd, x01.x, aG[1][0]);
        aG[1][1] = ffma2(wd, x01.y, aG[1][1]);
        aG[1][2] = ffma2(wd, x23.x, aG[1][2]);
        aG[1][3] = ffma2(wd, x23.y, aG[1][3]);
        wd = pack2(wg.z, wg.z);
        aG[2][0] = ffma2(wd, x01.x, aG[2][0]);
        aG[2][1] = ffma2(wd, x01.y, aG[2][1]);
        aG[2][2] = ffma2(wd, x23.x, aG[2][2]);
        aG[2][3] = ffma2(wd, x23.y, aG[2][3]);
        wd = pack2(wg.w, wg.w);
        aG[3][0] = ffma2(wd, x01.x, aG[3][0]);
        aG[3][1] = ffma2(wd, x01.y, aG[3][1]);
        aG[3][2] = ffma2(wd, x23.x, aG[3][2]);
        aG[3][3] = ffma2(wd, x23.y, aG[3][3]);
    }

    // ---- activation: z = tanh(a) * sigmoid(g) ----
    float z[4][8];
#pragma unroll
    for (int c = 0; c < 4; c++) {
#pragma unroll
        for (int p = 0; p < 4; p++) {
            float2 av = unpack2(aF[c][p]);
            float2 gv = unpack2(aG[c][p]);
            z[c][2 * p]     = tanh_approx(av.x) * fmaf(0.5f, tanh_approx(0.5f * gv.x), 0.5f);
            z[c][2 * p + 1] = tanh_approx(av.y) * fmaf(0.5f, tanh_approx(0.5f * gv.y), 0.5f);
        }
    }

    const int base = t0 + pg * 8;
    if (last) {     // layer 39: store z only (uniform branch)
        float* obB = xout + (size_t)b * 32 * W;
#pragma unroll
        for (int c = 0; c < 4; c++) {
            float* obc = obB + (og * 4 + c) * W + base;
#pragma unroll
            for (int j = 0; j < 8; j++)
                if (base + j < W) obc[j] = z[c][j];
        }
        return;
    }

    // ---- save cur x for residual-add (rows 2c+1, before z overwrite) ----
    unsigned long long acc[4][4];
#pragma unroll
    for (int c = 0; c < 4; c++) {
        const float* xr = sX + ((og * 4 + c) * 2 + 1) * 128 + pg * 8;
        ulonglong2 u = *(const ulonglong2*)xr;
        ulonglong2 v = *(const ulonglong2*)(xr + 4);
        acc[c][0] = u.x; acc[c][1] = u.y; acc[c][2] = v.x; acc[c][3] = v.y;
    }
    __syncthreads();

    // ---- write z into sX rows 0..31; stage dup'd resid weights ----
#pragma unroll
    for (int c = 0; c < 4; c++) {
        ulonglong2 z01, z23;
        z01.x = pack2(z[c][0], z[c][1]);
        z01.y = pack2(z[c][2], z[c][3]);
        z23.x = pack2(z[c][4], z[c][5]);
        z23.y = pack2(z[c][6], z[c][7]);
        float* zr = sX + (og * 4 + c) * 128 + pg * 8;
        *(ulonglong2*)zr = z01;
        *(ulonglong2*)(zr + 4) = z23;
    }
    unsigned long long* sRW = (unsigned long long*)(smem + 8192);
#pragma unroll
    for (int i = tid; i < 1024; i += 128) {
        float v = resid[i];                       // resid[c*32 + in]
        sRW[(i & 31) * 34 + (i >> 5)] = pack2(v, v);
    }
    __syncthreads();

    // ---- residual GEMM: 32 k-steps, 16 FFMA2 per step ----
#pragma unroll 8
    for (int k = 0; k < 32; k++) {
        const float* zr = sX + k * 128 + pg * 8;
        ulonglong2 za = *(const ulonglong2*)zr;
        ulonglong2 zb = *(const ulonglong2*)(zr + 4);
        const unsigned long long* wr = sRW + k * 34 + og * 4;
        ulonglong2 w01 = *(const ulonglong2*)wr;
        ulonglong2 w23 = *(const ulonglong2*)(wr + 2);
        acc[0][0] = ffma2(w01.x, za.x, acc[0][0]);
        acc[0][1] = ffma2(w01.x, za.y, acc[0][1]);
        acc[0][2] = ffma2(w01.x, zb.x, acc[0][2]);
        acc[0][3] = ffma2(w01.x, zb.y, acc[0][3]);
        acc[1][0] = ffma2(w01.y, za.x, acc[1][0]);
        acc[1][1] = ffma2(w01.y, za.y, acc[1][1]);
        acc[1][2] = ffma2(w01.y, zb.x, acc[1][2]);
        acc[1][3] = ffma2(w01.y, zb.y, acc[1][3]);
        acc[2][0] = ffma2(w23.x, za.x, acc[2][0]);
        acc[2][1] = ffma2(w23.x, za.y, acc[2][1]);
        acc[2][2] = ffma2(w23.x, zb.x, acc[2][2]);
        acc[2][3] = ffma2(w23.x, zb.y, acc[2][3]);
        acc[3][0] = ffma2(w23.y, za.x, acc[3][0]);
        acc[3][1] = ffma2(w23.y, za.y, acc[3][1]);
        acc[3][2] = ffma2(w23.y, zb.x, acc[3][2]);
        acc[3][3] = ffma2(w23.y, zb.y, acc[3][3]);
    }

    float* obB = xout + (size_t)b * 32 * W;
#pragma unroll
    for (int c = 0; c < 4; c++) {
        float* obc = obB + (og * 4 + c) * W + base;
#pragma unroll
        for (int p = 0; p < 4; p++) {
            float2 o = unpack2(acc[c][p]);
            if (base + 2 * p < W)     obc[2 * p]     = o.x;
            if (base + 2 * p + 1 < W) obc[2 * p + 1] = o.y;
        }
    }
}

// ---------------------------------------------------------------------------
// Fused head: out = e2 @ relu(e1 @ relu(skip39 @ z) + b1) + b2
// (verified R14 version; layer 39 writes z into g_bufA)
// ---------------------------------------------------------------------------
__global__ __launch_bounds__(256) void head_fused_kernel(
    const float* __restrict__ skip39, const float* __restrict__ e1,
    const float* __restrict__ b1, const float* __restrict__ e2,
    const float* __restrict__ b2, float* __restrict__ out)
{
    __shared__ __align__(16) float zt[32 * 32];
    __shared__ __align__(16) float s_sm[256 * 32];

    const int b  = blockIdx.y;
    const int j0 = blockIdx.x * 32;
    const int tid = threadIdx.x;
    const int p = tid & 31, g = tid >> 5;

    const float* zsrc = g_bufA + (size_t)b * 32 * W + 4096 + j0;
#pragma unroll
    for (int it = 0; it < 4; it++) {
        int r = it * 8 + g;
        zt[r * 32 + p] = zsrc[(size_t)r * W + p];
    }
    __syncthreads();

    float zr[32];
#pragma unroll
    for (int r = 0; r < 32; r++) zr[r] = zt[r * 32 + p];

#pragma unroll 4
    for (int cl = 0; cl < 32; cl++) {
        int c = g * 32 + cl;
        const float4* skv = (const float4*)(skip39 + c * 32);
        float a0 = 0.f, a1 = 0.f;
#pragma unroll
        for (int r4 = 0; r4 < 8; r4++) {
            float4 w = __ldg(&skv[r4]);
            a0 = fmaf(w.x, zr[4 * r4 + 0], a0);
            a1 = fmaf(w.y, zr[4 * r4 + 1], a1);
            a0 = fmaf(w.z, zr[4 * r4 + 2], a0);
            a1 = fmaf(w.w, zr[4 * r4 + 3], a1);
        }
        s_sm[c * 32 + p] = fmaxf(a0 + a1, 0.f);
    }
    __syncthreads();

    unsigned long long accp[16];
#pragma unroll
    for (int i = 0; i < 16; i++) accp[i] = 0ull;

    const float4* e1row = (const float4*)(e1 + tid * 256);
    for (int s4i = 0; s4i < 64; s4i++) {
        float4 w4 = __ldg(e1row + s4i);
        const float ws[4] = {w4.x, w4.y, w4.z, w4.w};
#pragma unroll
        for (int ss = 0; ss < 4; ss++) {
            unsigned long long wd = pack2(ws[ss], ws[ss]);
            const ulonglong2* sv = (const ulonglong2*)(s_sm + (s4i * 4 + ss) * 32);
#pragma unroll
            for (int q = 0; q < 8; q++) {
                ulonglong2 sx = sv[q];
                accp[2 * q]     = ffma2(wd, sx.x, accp[2 * q]);
                accp[2 * q + 1] = ffma2(wd, sx.y, accp[2 * q + 1]);
            }
        }
    }

    float h[32];
    {
        float bias1 = b1[tid];
#pragma unroll
        for (int q = 0; q < 8; q++) {
            float2 u = unpack2(accp[2 * q]);
            float2 v = unpack2(accp[2 * q + 1]);
            h[4 * q + 0] = fmaxf(u.x + bias1, 0.f);
            h[4 * q + 1] = fmaxf(u.y + bias1, 0.f);
            h[4 * q + 2] = fmaxf(v.x + bias1, 0.f);
            h[4 * q + 3] = fmaxf(v.y + bias1, 0.f);
        }
    }

    __syncthreads();
    {
        float4* dst = (float4*)(s_sm + tid * 32);
#pragma unroll
        for (int q = 0; q < 8; q++)
            dst[q] = make_float4(h[4 * q], h[4 * q + 1], h[4 * q + 2], h[4 * q + 3]);
    }
    __syncthreads();

#pragma unroll
    for (int i = 0; i < 16; i++) accp[i] = 0ull;

    const float4* e2row = (const float4*)(e2 + tid * 256);
    for (int s4i = 0; s4i < 64; s4i++) {
        float4 w4 = __ldg(e2row + s4i);
        const float ws[4] = {w4.x, w4.y, w4.z, w4.w};
#pragma unroll
        for (int ss = 0; ss < 4; ss++) {
            unsigned long long wd = pack2(ws[ss], ws[ss]);
            const ulonglong2* hv = (const ulonglong2*)(s_sm + (s4i * 4 + ss) * 32);
#pragma unroll
            for (int q = 0; q < 8; q++) {
                ulonglong2 hx = hv[q];
                accp[2 * q]     = ffma2(wd, hx.x, accp[2 * q]);
                accp[2 * q + 1] = ffma2(wd, hx.y, accp[2 * q + 1]);
            }
        }
    }

    float bias2 = b2[tid];
    float* ob = out + ((size_t)b * 4096 + j0) * 256 + tid;
#pragma unroll
    for (int q = 0; q < 8; q++) {
        float2 u = unpack2(accp[2 * q]);
        float2 v = unpack2(accp[2 * q + 1]);
        ob[(size_t)(4 * q + 0) * 256] = u.x + bias2;
        ob[(size_t)(4 * q + 1) * 256] = u.y + bias2;
        ob[(size_t)(4 * q + 2) * 256] = v.x + bias2;
        ob[(size_t)(4 * q + 3) * 256] = v.y + bias2;
    }
}

// ---------------------------------------------------------------------------

extern "C" void kernel_launch(void* const* d_in, const int* in_sizes, int n_in,
                              void* d_out, int out_size)
{
    (void)in_sizes; (void)n_in; (void)out_size;
    const float* x_input    = (const float*)d_in[0];
    const float* start_w    = (const float*)d_in[1];
    const float* filter_w   = (const float*)d_in[2];
    const float* gate_w     = (const float*)d_in[3];
    const float* residual_w = (const float*)d_in[4];
    const float* skip_w     = (const float*)d_in[5];
    const float* e1         = (const float*)d_in[6];
    const float* b1         = (const float*)d_in[7];
    const float* e2         = (const float*)d_in[8];
    const float* b2         = (const float*)d_in[9];
    float* out = (float*)d_out;

    const int LAYER_SMEM = 12544 * 4;   // 49 KB dynamic
    cudaFuncSetAttribute(layer_kernel,
                         cudaFuncAttributeMaxDynamicSharedMemorySize,
                         LAYER_SMEM);

    // dilations: 4 blocks of 1,2,4,...,512
    int ds[40];
    {
        int idx = 0;
        for (int blk = 0; blk < 4; blk++) {
            int nd = 1;
            for (int l = 0; l < 10; l++) { ds[idx++] = nd; nd *= 2; }
        }
    }
    // S[i] = 4096 - sum_{j>i} ds[j]  (valid output start for layer i)
    int S[40];
    {
        int suf = 0;
        for (int i = 39; i >= 0; i--) { S[i] = 4096 - suf; suf += ds[i]; }
    }

    start_kernel<<<dim3(32, 8), 128>>>(x_input, start_w);

    for (int i = 0; i < 40; i++) {
        int tstart = S[i];
        int n = W - tstart;
        int gx = (n + 127) / 128;
        layer_kernel<<<dim3(gx, 8), 128, LAYER_SMEM>>>(
            filter_w + (size_t)i * 2048, gate_w + (size_t)i * 2048,
            residual_w + (size_t)i * 1024,
            ds[i], tstart, i & 1, (i == 39) ? 1 : 0);
    }

    head_fused_kernel<<<dim3(128, 8), 256>>>(
        skip_w + (size_t)39 * 256 * 32, e1, b1, e2, b2, out);
}